// round 1
// baseline (speedup 1.0000x reference)
#include <cuda_runtime.h>
#include <math.h>

// ---------------------------------------------------------------------------
// KANConv2d: B=4, C=64, H=W=64, out=128, 3x3 conv, pad 1.
// Reformulated: expanded feature map F (silu + 8 uniform cubic B-spline
// basis channels per input channel) followed by a single 3x3 conv
// (implicit GEMM, M=16384, N=128, K=5184).
// ---------------------------------------------------------------------------

#define BATCH 4
#define CIN 64
#define HH 64
#define WW 64
#define OUTC 128
#define PH 66           // padded H
#define PW 66           // padded W
#define CF 576          // 64 channels * 9 (silu + 8 basis)
#define KTOT 5184       // 9 taps * 576
#define NKS 648         // 5184 / 8

// scratch (device globals: allocation-free)
__device__ float g_F[BATCH * PH * PW * CF];     // ~40.1 MB, padded NHWC features
__device__ float g_B[KTOT * OUTC];              // ~2.65 MB, folded weights [kk][o]

// ---------------------------------------------------------------------------
// per-element features: silu + 8 cubic B-spline basis values
// grid knots t_i = (i-3)*0.4 - 1, i = 0..11; interval j in [0,10]
// ---------------------------------------------------------------------------
__device__ __forceinline__ void feat9(float v, float* dst) {
    dst[0] = v / (1.0f + expf(-v));            // silu
    float s = (v + 2.2f) * 2.5f;               // (v - t0) / h
    int j = (int)floorf(s);
    float B0 = 0.f, B1 = 0.f, B2 = 0.f, B3 = 0.f;
    if (j >= 0 && j <= 10) {
        float u  = (v - (0.4f * (float)j - 2.2f)) * 2.5f;  // local coord in [0,1)
        float um = 1.0f - u;
        float u2 = u * u;
        float u3 = u2 * u;
        B3 = u3 * (1.0f / 6.0f);                                     // basis i = j
        B2 = (-3.0f*u3 + 3.0f*u2 + 3.0f*u + 1.0f) * (1.0f/6.0f);     // i = j-1
        B1 = ( 3.0f*u3 - 6.0f*u2 + 4.0f) * (1.0f/6.0f);              // i = j-2
        B0 = um * um * um * (1.0f / 6.0f);                           // i = j-3
    }
#pragma unroll
    for (int i = 0; i < 8; i++) {
        int rel = j - i;
        float val = (rel == 0) ? B3 : (rel == 1) ? B2 : (rel == 2) ? B1
                  : (rel == 3) ? B0 : 0.0f;
        dst[1 + i] = val;
    }
}

// ---------------------------------------------------------------------------
// Feature kernel: grid (PH, BATCH), 256 threads.
// Border pixels = features of x=0 (reference's im2col includes the zero pad,
// and basis(0) != 0).
// ---------------------------------------------------------------------------
__global__ __launch_bounds__(256) void feat_kernel(const float* __restrict__ x) {
    int y   = blockIdx.x;   // 0..65 padded row
    int b   = blockIdx.y;
    int tid = threadIdx.x;
    float* row = g_F + ((size_t)(b * PH + y)) * PW * CF;

    float zf[9];
    feat9(0.0f, zf);

    if (y == 0 || y == PH - 1) {
        for (int idx = tid; idx < PW * CF; idx += 256) {
            int cf = idx % CF;
            row[idx] = zf[cf % 9];
        }
        return;
    }
    // left / right border columns
    for (int idx = tid; idx < 2 * CF; idx += 256) {
        int side = idx / CF;
        int cf   = idx % CF;
        row[(size_t)(side * (PW - 1)) * CF + cf] = zf[cf % 9];
    }
    int iy = y - 1;
    int xx = tid & 63;
    for (int c = tid >> 6; c < CIN; c += 4) {
        float v = x[(((b * CIN + c) * HH + iy) << 6) + xx];
        float f[9];
        feat9(v, f);
        float* dst = row + (size_t)(xx + 1) * CF + c * 9;
#pragma unroll
        for (int q = 0; q < 9; q++) dst[q] = f[q];
    }
}

// ---------------------------------------------------------------------------
// Weight fold: g_B[kk*128 + o], kk = tap*576 + c*9 + ck
//   ck=0      -> base_weight[o, d]
//   ck=1..8   -> spline_weight[o, d, ck-1] * spline_scaler[o, d]
// with d = c*9 + tap (F.unfold (C,kh,kw) order).
// ---------------------------------------------------------------------------
__global__ __launch_bounds__(256) void weight_kernel(
    const float* __restrict__ bw, const float* __restrict__ sw,
    const float* __restrict__ ss) {
    int idx = blockIdx.x * 256 + threadIdx.x;
    if (idx >= KTOT * OUTC) return;
    int o   = idx & 127;
    int kk  = idx >> 7;
    int tap = kk / 576;
    int r   = kk - tap * 576;
    int c   = r / 9;
    int ck  = r - c * 9;
    int d   = c * 9 + tap;
    float val;
    if (ck == 0) val = bw[o * 576 + d];
    else         val = sw[(o * 576 + d) * 8 + (ck - 1)] * ss[o * 576 + d];
    g_B[idx] = val;
}

// ---------------------------------------------------------------------------
// Implicit-GEMM conv. M=16384 positions, N=128 out channels, K=5184.
// Block tile 128x128, K-step 8, double buffered, 256 threads, 8x8/thread.
// ---------------------------------------------------------------------------
__global__ __launch_bounds__(256) void gemm_kernel(float* __restrict__ out) {
    __shared__ float As[2][8][128];
    __shared__ float Bs[2][8][128];

    const int tid   = threadIdx.x;
    const int mbase = blockIdx.x * 128;

    // --- A-load mapping: each thread loads one float4 (m = tid/2, half = tid&1)
    const int m    = tid >> 1;
    const int half = tid & 1;
    const int n    = mbase + m;
    const int pb   = n >> 12;
    const int oy   = (n >> 6) & 63;
    const int ox   = n & 63;
    const float* apix = g_F + ((size_t)((pb * PH + oy) * PW + ox)) * CF + half * 4;

    const int tx = tid & 15;
    const int ty = tid >> 4;

    float4 av, bv;

    // prologue: slice 0 (tap 0, rcf 0)
    av = *(const float4*)(apix);
    bv = *(const float4*)(g_B + tid * 4);

    {
        int kk0 = half * 4;
        As[0][kk0 + 0][m] = av.x;
        As[0][kk0 + 1][m] = av.y;
        As[0][kk0 + 2][m] = av.z;
        As[0][kk0 + 3][m] = av.w;
        *(float4*)&Bs[0][tid >> 5][(tid * 4) & 127] = bv;
    }
    __syncthreads();

    float acc[8][8];
#pragma unroll
    for (int i = 0; i < 8; i++)
#pragma unroll
        for (int j = 0; j < 8; j++) acc[i][j] = 0.0f;

    for (int ks = 0; ks < NKS; ks++) {
        const int cur = ks & 1;
        if (ks + 1 < NKS) {
            int ksn = ks + 1;
            int tap = ksn / 72;
            int rcf = (ksn - tap * 72) * 8;
            int kh  = tap / 3;
            int kw  = tap - kh * 3;
            av = *(const float4*)(apix + (kh * PW + kw) * CF + rcf);
            bv = *(const float4*)(g_B + (size_t)ksn * 1024 + tid * 4);
        }

#pragma unroll
        for (int kki = 0; kki < 8; kki++) {
            float4 a0 = *(const float4*)&As[cur][kki][ty * 8];
            float4 a1 = *(const float4*)&As[cur][kki][ty * 8 + 4];
            float4 b0 = *(const float4*)&Bs[cur][kki][tx * 8];
            float4 b1 = *(const float4*)&Bs[cur][kki][tx * 8 + 4];
            float ar[8] = {a0.x, a0.y, a0.z, a0.w, a1.x, a1.y, a1.z, a1.w};
            float br[8] = {b0.x, b0.y, b0.z, b0.w, b1.x, b1.y, b1.z, b1.w};
#pragma unroll
            for (int i = 0; i < 8; i++)
#pragma unroll
                for (int j = 0; j < 8; j++) acc[i][j] += ar[i] * br[j];
        }

        if (ks + 1 < NKS) {
            int nb  = cur ^ 1;
            int kk0 = half * 4;
            As[nb][kk0 + 0][m] = av.x;
            As[nb][kk0 + 1][m] = av.y;
            As[nb][kk0 + 2][m] = av.z;
            As[nb][kk0 + 3][m] = av.w;
            *(float4*)&Bs[nb][tid >> 5][(tid * 4) & 127] = bv;
            __syncthreads();
        }
    }

    // epilogue: out[b, o, oy, ox]; rows m are spatially consecutive -> float4
    const int orow = mbase + ty * 8;
    const int b_   = orow >> 12;
    const int sp   = orow & 4095;
#pragma unroll
    for (int j = 0; j < 8; j++) {
        int o = tx * 8 + j;
        float4 v0 = make_float4(acc[0][j], acc[1][j], acc[2][j], acc[3][j]);
        float4 v1 = make_float4(acc[4][j], acc[5][j], acc[6][j], acc[7][j]);
        float* op = out + ((size_t)(b_ * OUTC + o) << 12) + sp;
        *(float4*)op       = v0;
        *(float4*)(op + 4) = v1;
    }
}

// ---------------------------------------------------------------------------
extern "C" void kernel_launch(void* const* d_in, const int* in_sizes, int n_in,
                              void* d_out, int out_size) {
    const float* x  = (const float*)d_in[0];   // (4,64,64,64)
    const float* bw = (const float*)d_in[1];   // (128,576)
    const float* sw = (const float*)d_in[2];   // (128,576,8)
    const float* ss = (const float*)d_in[3];   // (128,576)
    float* out = (float*)d_out;                // (4,128,64,64)

    dim3 gf(PH, BATCH);
    feat_kernel<<<gf, 256>>>(x);
    weight_kernel<<<(KTOT * OUTC + 255) / 256, 256>>>(bw, sw, ss);
    gemm_kernel<<<16384 / 128, 256>>>(out);
}

// round 3
// speedup vs baseline: 2.3272x; 2.3272x over previous
#include <cuda_runtime.h>
#include <cuda_bf16.h>
#include <cstdint>
#include <math.h>

// ---------------------------------------------------------------------------
// KANConv2d: expanded feature map (silu + 8 uniform cubic B-spline basis
// channels per input channel) -> single 3x3 conv as implicit GEMM.
// Tensor path: mma.sync bf16 (sm_80-compatible; tcgen05 is blocked because the
// harness PTX target is compute_103 without the 'a' feature suffix).
// Precision: bf16 hi/lo split, 3 MMA passes (Ah*Bh + Ah*Bl + Al*Bh), fp32 acc.
// ---------------------------------------------------------------------------

#define BATCH 4
#define CIN 64
#define OUTC 128
#define PH 66
#define PW 66
#define CF 576          // 64 ch * 9 feats
#define KTOT 5184       // 9 taps * 576
#define NCHUNK 81       // 5184 / 64

// device scratch (allocation-free)
__device__ __align__(16) __nv_bfloat16 g_Fh[BATCH * PH * PW * CF];
__device__ __align__(16) __nv_bfloat16 g_Fl[BATCH * PH * PW * CF];
__device__ __align__(16) __nv_bfloat16 g_Bh[OUTC * KTOT];
__device__ __align__(16) __nv_bfloat16 g_Bl[OUTC * KTOT];

// ---------------------------------------------------------------------------
__device__ __forceinline__ uint32_t smem_u32(const void* p) {
    uint32_t a;
    asm("{ .reg .u64 t; cvta.to.shared.u64 t, %1; cvt.u32.u64 %0, t; }"
        : "=r"(a) : "l"(p));
    return a;
}

#define CP16(dst, src) \
    asm volatile("cp.async.cg.shared.global [%0], [%1], 16;" \
                 :: "r"(dst), "l"(src) : "memory")
#define CP_COMMIT() asm volatile("cp.async.commit_group;" ::: "memory")
#define CP_WAIT(n)  asm volatile("cp.async.wait_group %0;" :: "n"(n) : "memory")

#define LDSM4(r0, r1, r2, r3, a) \
    asm volatile("ldmatrix.sync.aligned.m8n8.x4.shared.b16 {%0,%1,%2,%3}, [%4];" \
                 : "=r"(r0), "=r"(r1), "=r"(r2), "=r"(r3) : "r"(a))

#define MMA16816(d, a, b0, b1) \
    asm volatile("mma.sync.aligned.m16n8k16.row.col.f32.bf16.bf16.f32 " \
                 "{%0,%1,%2,%3}, {%4,%5,%6,%7}, {%8,%9}, {%0,%1,%2,%3};" \
                 : "+f"((d)[0]), "+f"((d)[1]), "+f"((d)[2]), "+f"((d)[3]) \
                 : "r"((a)[0]), "r"((a)[1]), "r"((a)[2]), "r"((a)[3]), \
                   "r"(b0), "r"(b1))

// ---------------------------------------------------------------------------
// feature math: silu + 8 uniform cubic B-spline basis values (grid [-2.2,2.2])
// ---------------------------------------------------------------------------
__device__ __forceinline__ void feat9(float v, float* dst) {
    dst[0] = v / (1.0f + __expf(-v));
    float s = (v + 2.2f) * 2.5f;
    int j = (int)floorf(s);
    float B0 = 0.f, B1 = 0.f, B2 = 0.f, B3 = 0.f;
    if (j >= 0 && j <= 10) {
        float u  = (v - (0.4f * (float)j - 2.2f)) * 2.5f;
        float um = 1.0f - u;
        float u2 = u * u, u3 = u2 * u;
        B3 = u3 * (1.0f / 6.0f);
        B2 = (-3.0f * u3 + 3.0f * u2 + 3.0f * u + 1.0f) * (1.0f / 6.0f);
        B1 = (3.0f * u3 - 6.0f * u2 + 4.0f) * (1.0f / 6.0f);
        B0 = um * um * um * (1.0f / 6.0f);
    }
#pragma unroll
    for (int i = 0; i < 8; i++) {
        int rel = j - i;
        dst[1 + i] = (rel == 0) ? B3 : (rel == 1) ? B2 : (rel == 2) ? B1
                   : (rel == 3) ? B0 : 0.0f;
    }
}

__device__ __forceinline__ void split2(float v, __nv_bfloat16& h, __nv_bfloat16& l) {
    h = __float2bfloat16(v);
    l = __float2bfloat16(v - __bfloat162float(h));
}

// ---------------------------------------------------------------------------
// feat kernel: interior pixels. grid (2, 64, 4) = (x-half, row, batch).
// ---------------------------------------------------------------------------
__global__ __launch_bounds__(256) void feat_kernel(const float* __restrict__ x) {
    extern __shared__ char dynsm[];
    float* slab   = reinterpret_cast<float*>(dynsm);                 // 8448 B
    uint32_t* stH = reinterpret_cast<uint32_t*>(dynsm + 8448);       // 36992 B
    uint32_t* stL = reinterpret_cast<uint32_t*>(dynsm + 8448 + 36992);

    const int tid = threadIdx.x;
    const int xb  = blockIdx.x * 32;
    const int iy  = blockIdx.y;
    const int b   = blockIdx.z;

    for (int i = tid; i < 64 * 32; i += 256) {
        int c = i >> 5, px = i & 31;
        slab[c * 33 + px] = x[(((b * 64 + c) * 64 + iy) << 6) + xb + px];
    }
    __syncthreads();

    const int px = tid >> 3;
    const int cg = tid & 7;
#pragma unroll
    for (int pair = 0; pair < 4; pair++) {
        int c0 = cg * 8 + pair * 2;
        float f[18];
        feat9(slab[c0 * 33 + px], f);
        feat9(slab[(c0 + 1) * 33 + px], f + 9);
        int wb = px * 289 + cg * 36 + pair * 9;
#pragma unroll
        for (int q = 0; q < 9; q++) {
            __nv_bfloat16 ah, al, bh, bl;
            split2(f[2 * q], ah, al);
            split2(f[2 * q + 1], bh, bl);
            __nv_bfloat162 th = __halves2bfloat162(ah, bh);
            __nv_bfloat162 tl = __halves2bfloat162(al, bl);
            stH[wb + q] = *reinterpret_cast<uint32_t*>(&th);
            stL[wb + q] = *reinterpret_cast<uint32_t*>(&tl);
        }
    }
    __syncthreads();

    const size_t pixbase = ((size_t)((b * PH + iy + 1) * PW + xb + 1)) * CF;
    uint32_t* dH = reinterpret_cast<uint32_t*>(g_Fh + pixbase);
    uint32_t* dL = reinterpret_cast<uint32_t*>(g_Fl + pixbase);
    for (int i = tid; i < 32 * 288; i += 256) {
        int p = i / 288, w = i - p * 288;
        dH[i] = stH[p * 289 + w];
        dL[i] = stL[p * 289 + w];
    }
}

// ---------------------------------------------------------------------------
// border kernel: padded border pixels get features of x = 0
// ---------------------------------------------------------------------------
__global__ __launch_bounds__(256) void border_kernel() {
    int i = blockIdx.x;
    int b = i / 260, r = i - b * 260;
    int py, pxx;
    if (r < 66)        { py = 0;  pxx = r; }
    else if (r < 132)  { py = 65; pxx = r - 66; }
    else { int t = r - 132; py = 1 + (t >> 1); pxx = (t & 1) * 65; }

    float zf[9];
    feat9(0.0f, zf);
    __nv_bfloat16 zh[9], zl[9];
#pragma unroll
    for (int q = 0; q < 9; q++) split2(zf[q], zh[q], zl[q]);

    __nv_bfloat16* dH = g_Fh + ((size_t)((b * PH + py) * PW + pxx)) * CF;
    __nv_bfloat16* dL = g_Fl + ((size_t)((b * PH + py) * PW + pxx)) * CF;
    for (int e = threadIdx.x; e < CF; e += 256) {
        int q = e % 9;
        dH[e] = zh[q];
        dL[e] = zl[q];
    }
}

// ---------------------------------------------------------------------------
// weight fold -> [o][kk], kk = tap*576 + c*9 + ck, source index d = c*9 + tap
// ---------------------------------------------------------------------------
__global__ __launch_bounds__(256) void weight_kernel(
    const float* __restrict__ bw, const float* __restrict__ sw,
    const float* __restrict__ ss) {
    int idx = blockIdx.x * 256 + threadIdx.x;
    if (idx >= OUTC * KTOT) return;
    int o   = idx / KTOT;
    int kk  = idx - o * KTOT;
    int tap = kk / 576;
    int r   = kk - tap * 576;
    int c   = r / 9;
    int ck  = r - c * 9;
    int d   = c * 9 + tap;
    float v = ck ? sw[(o * 576 + d) * 8 + (ck - 1)] * ss[o * 576 + d]
                 : bw[o * 576 + d];
    __nv_bfloat16 h, l;
    split2(v, h, l);
    g_Bh[idx] = h;
    g_Bl[idx] = l;
}

// ---------------------------------------------------------------------------
// GEMM: 128 CTAs, M=128 x N=128 x K=5184, bf16 hi/lo x3 via mma.sync.
// K in 64-element chunks; double-buffered SMEM, cp.async, ldmatrix.
// Per buffer (64KB): [Ah 16K][Al 16K][Bh 16K][Bl 16K], rows of 128B, swizzled.
// 8 warps: warp (wm = wid&3, wn = wid>>2) computes m32 x n64.
// ---------------------------------------------------------------------------
#define BUF_BYTES 65536
#define T_AH 0
#define T_AL 16384
#define T_BH 32768
#define T_BL 49152

__global__ __launch_bounds__(256, 1) void gemm_kernel(float* __restrict__ out) {
    extern __shared__ char dynsm[];
    uint32_t raw  = smem_u32(dynsm);
    uint32_t base = (raw + 1023u) & ~1023u;

    const int tid  = threadIdx.x;
    const int wid  = tid >> 5;
    const int lane = tid & 31;
    const int wm   = wid & 3;
    const int wn   = wid >> 2;
    const int mbase = blockIdx.x * 128;

    // ---- cp.async source/dest mapping: row = tid>>1, seg = tid&1 ----
    const int row = tid >> 1;
    const int seg = tid & 1;
    {
        // nothing
    }
    const int npix = mbase + row;
    const int pb = npix >> 12;
    const int oy = (npix >> 6) & 63;
    const int ox = npix & 63;
    const __nv_bfloat16* apH = g_Fh + ((size_t)((pb * PH + oy) * PW + ox)) * CF;
    const __nv_bfloat16* apL = g_Fl + ((size_t)((pb * PH + oy) * PW + ox)) * CF;
    const __nv_bfloat16* bpH = g_Bh + (size_t)row * KTOT;
    const __nv_bfloat16* bpL = g_Bl + (size_t)row * KTOT;
    const uint32_t rowterm = (uint32_t)row * 128;
    const uint32_t rowpat  = ((uint32_t)row & 7) << 4;

    auto load_chunk = [&](int kc, uint32_t bufoff) {
        int tap = kc / 9;
        int sub = kc - tap * 9;
        int kh = tap / 3, kw = tap - kh * 3;
        int aoff = (kh * PW + kw) * CF + sub * 64 + seg * 32;  // elements
        int boff = kc * 64 + seg * 32;
        const char* sAh = (const char*)(apH + aoff);
        const char* sAl = (const char*)(apL + aoff);
        const char* sBh = (const char*)(bpH + boff);
        const char* sBl = (const char*)(bpL + boff);
#pragma unroll
        for (int q = 0; q < 4; q++) {
            uint32_t kb = (uint32_t)(seg * 64 + q * 16);
            uint32_t d  = base + bufoff + rowterm + (kb ^ rowpat);
            CP16(d + T_AH, sAh + q * 16);
            CP16(d + T_AL, sAl + q * 16);
            CP16(d + T_BH, sBh + q * 16);
            CP16(d + T_BL, sBl + q * 16);
        }
        CP_COMMIT();
    };

    // ---- ldmatrix lane addressing ----
    // A: lanes 0-15 -> rows 0-15 @ k, lanes 16-31 -> rows 0-15 @ k+8
    const int rA  = lane & 15;
    const uint32_t kA = ((uint32_t)(lane >> 4)) * 16;   // bytes
    uint32_t aRow[2], aPat[2];
#pragma unroll
    for (int mt = 0; mt < 2; mt++) {
        int rr = wm * 32 + mt * 16 + rA;
        aRow[mt] = (uint32_t)rr * 128;
        aPat[mt] = ((uint32_t)rr & 7) << 4;
    }
    // B: lanes 0-7: n0-7@k, 8-15: n0-7@k+8, 16-23: n8-15@k, 24-31: n8-15@k+8
    const int rBl = (lane & 7) + ((lane >> 4) & 1) * 8;
    const uint32_t kB = ((uint32_t)((lane >> 3) & 1)) * 16;
    uint32_t bRow[4], bPat[4];
#pragma unroll
    for (int nt = 0; nt < 4; nt++) {
        int rr = wn * 64 + nt * 16 + rBl;
        bRow[nt] = (uint32_t)rr * 128;
        bPat[nt] = ((uint32_t)rr & 7) << 4;
    }

    float acc[2][8][4];
#pragma unroll
    for (int i = 0; i < 2; i++)
#pragma unroll
        for (int j = 0; j < 8; j++)
#pragma unroll
            for (int q = 0; q < 4; q++) acc[i][j][q] = 0.0f;

    load_chunk(0, 0);

    for (int ks = 0; ks < NCHUNK; ks++) {
        const uint32_t cur = (uint32_t)(ks & 1);
        if (ks + 1 < NCHUNK) {
            load_chunk(ks + 1, (cur ^ 1u) * BUF_BYTES);
            CP_WAIT(1);
        } else {
            CP_WAIT(0);
        }
        __syncthreads();

        const uint32_t bb = base + cur * BUF_BYTES;
#pragma unroll
        for (int kk = 0; kk < 4; kk++) {
            uint32_t ah[2][4], al[2][4];
#pragma unroll
            for (int mt = 0; mt < 2; mt++) {
                uint32_t koff = ((uint32_t)(kk * 32) + kA) ^ aPat[mt];
                uint32_t addr = bb + aRow[mt] + koff;
                LDSM4(ah[mt][0], ah[mt][1], ah[mt][2], ah[mt][3], addr + T_AH);
                LDSM4(al[mt][0], al[mt][1], al[mt][2], al[mt][3], addr + T_AL);
            }
#pragma unroll
            for (int nt = 0; nt < 4; nt++) {
                uint32_t koff = ((uint32_t)(kk * 32) + kB) ^ bPat[nt];
                uint32_t addr = bb + bRow[nt] + koff;
                uint32_t bh[4], bl[4];
                LDSM4(bh[0], bh[1], bh[2], bh[3], addr + T_BH);
                LDSM4(bl[0], bl[1], bl[2], bl[3], addr + T_BL);
#pragma unroll
                for (int mt = 0; mt < 2; mt++) {
#pragma unroll
                    for (int sub = 0; sub < 2; sub++) {
                        float* d = acc[mt][nt * 2 + sub];
                        MMA16816(d, ah[mt], bh[sub * 2], bh[sub * 2 + 1]);
                        MMA16816(d, ah[mt], bl[sub * 2], bl[sub * 2 + 1]);
                        MMA16816(d, al[mt], bh[sub * 2], bh[sub * 2 + 1]);
                    }
                }
            }
        }
        __syncthreads();
    }

    // ---- epilogue: stage through smem (transpose), coalesced global write --
    float* st = reinterpret_cast<float*>(dynsm + (base - raw));
    const int g  = lane >> 2;
    const int tg = lane & 3;
#pragma unroll
    for (int mt = 0; mt < 2; mt++) {
#pragma unroll
        for (int n8 = 0; n8 < 8; n8++) {
            int m0 = wm * 32 + mt * 16 + g;
            int n0 = wn * 64 + n8 * 8 + tg * 2;
            const float* c = acc[mt][n8];
            st[m0 * 129 + n0]           = c[0];
            st[m0 * 129 + n0 + 1]       = c[1];
            st[(m0 + 8) * 129 + n0]     = c[2];
            st[(m0 + 8) * 129 + n0 + 1] = c[3];
        }
    }
    __syncthreads();

    const int b_ = mbase >> 12;
    const int spb = mbase & 4095;
#pragma unroll
    for (int r = 0; r < 64; r++) {
        int idx = r * 256 + tid;
        int o = idx >> 7;
        int m = idx & 127;
        out[(((size_t)(b_ * OUTC + o)) << 12) + spb + m] = st[m * 129 + o];
    }
}

// ---------------------------------------------------------------------------
extern "C" void kernel_launch(void* const* d_in, const int* in_sizes, int n_in,
                              void* d_out, int out_size) {
    const float* x  = (const float*)d_in[0];
    const float* bw = (const float*)d_in[1];
    const float* sw = (const float*)d_in[2];
    const float* ss = (const float*)d_in[3];
    float* out = (float*)d_out;

    cudaFuncSetAttribute(feat_kernel, cudaFuncAttributeMaxDynamicSharedMemorySize, 90112);
    cudaFuncSetAttribute(gemm_kernel, cudaFuncAttributeMaxDynamicSharedMemorySize, 133120);

    feat_kernel<<<dim3(2, 64, 4), 256, 8448 + 2 * 36992>>>(x);
    border_kernel<<<4 * 260, 256>>>();
    weight_kernel<<<(OUTC * KTOT + 255) / 256, 256>>>(bw, sw, ss);
    gemm_kernel<<<128, 256, 133120>>>(out);
}

// round 4
// speedup vs baseline: 3.5520x; 1.5263x over previous
#include <cuda_runtime.h>
#include <cuda_fp16.h>
#include <cstdint>
#include <math.h>

// ---------------------------------------------------------------------------
// KANConv2d: expanded feature map (silu + 8 uniform cubic B-spline basis
// channels per input channel) -> single 3x3 conv as implicit GEMM (mma.sync).
// Precision: A in fp16 hi/lo (exact to ~2^-22), B single fp16 plane.
// 2 MMA passes: Ah*B + Al*B, fp32 accumulate.
// ---------------------------------------------------------------------------

#define BATCH 4
#define CIN 64
#define OUTC 128
#define PH 66
#define PW 66
#define CF 576          // 64 ch * 9 feats
#define KTOT 5184       // 9 taps * 576
#define NCHUNK 81       // 5184 / 64

// device scratch (allocation-free)
__device__ __align__(16) __half g_Fh[BATCH * PH * PW * CF];
__device__ __align__(16) __half g_Fl[BATCH * PH * PW * CF];
__device__ __align__(16) __half g_Bf[OUTC * KTOT];

// ---------------------------------------------------------------------------
__device__ __forceinline__ uint32_t smem_u32(const void* p) {
    uint32_t a;
    asm("{ .reg .u64 t; cvta.to.shared.u64 t, %1; cvt.u32.u64 %0, t; }"
        : "=r"(a) : "l"(p));
    return a;
}

#define CP16(dst, src) \
    asm volatile("cp.async.cg.shared.global [%0], [%1], 16;" \
                 :: "r"(dst), "l"(src) : "memory")
#define CP_COMMIT() asm volatile("cp.async.commit_group;" ::: "memory")
#define CP_WAIT(n)  asm volatile("cp.async.wait_group %0;" :: "n"(n) : "memory")

#define LDSM4(r0, r1, r2, r3, a) \
    asm volatile("ldmatrix.sync.aligned.m8n8.x4.shared.b16 {%0,%1,%2,%3}, [%4];" \
                 : "=r"(r0), "=r"(r1), "=r"(r2), "=r"(r3) : "r"(a))

#define MMA16816(d, a, b0, b1) \
    asm volatile("mma.sync.aligned.m16n8k16.row.col.f32.f16.f16.f32 " \
                 "{%0,%1,%2,%3}, {%4,%5,%6,%7}, {%8,%9}, {%0,%1,%2,%3};" \
                 : "+f"((d)[0]), "+f"((d)[1]), "+f"((d)[2]), "+f"((d)[3]) \
                 : "r"((a)[0]), "r"((a)[1]), "r"((a)[2]), "r"((a)[3]), \
                   "r"(b0), "r"(b1))

// ---------------------------------------------------------------------------
// feature math: silu + 8 uniform cubic B-spline basis values (grid [-2.2,2.2])
// ---------------------------------------------------------------------------
__device__ __forceinline__ void feat9(float v, float* dst) {
    dst[0] = v / (1.0f + __expf(-v));
    float s = (v + 2.2f) * 2.5f;
    int j = (int)floorf(s);
    float B0 = 0.f, B1 = 0.f, B2 = 0.f, B3 = 0.f;
    if (j >= 0 && j <= 10) {
        float u  = (v - (0.4f * (float)j - 2.2f)) * 2.5f;
        float um = 1.0f - u;
        float u2 = u * u, u3 = u2 * u;
        B3 = u3 * (1.0f / 6.0f);
        B2 = (-3.0f * u3 + 3.0f * u2 + 3.0f * u + 1.0f) * (1.0f / 6.0f);
        B1 = (3.0f * u3 - 6.0f * u2 + 4.0f) * (1.0f / 6.0f);
        B0 = um * um * um * (1.0f / 6.0f);
    }
#pragma unroll
    for (int i = 0; i < 8; i++) {
        int rel = j - i;
        dst[1 + i] = (rel == 0) ? B3 : (rel == 1) ? B2 : (rel == 2) ? B1
                   : (rel == 3) ? B0 : 0.0f;
    }
}

__device__ __forceinline__ void split2h(float v, __half& h, __half& l) {
    h = __float2half_rn(v);
    l = __float2half_rn(v - __half2float(h));
}

// ---------------------------------------------------------------------------
// feat kernel: interior pixels. grid (2, 64, 4) = (x-half, row, batch).
// ---------------------------------------------------------------------------
__global__ __launch_bounds__(256) void feat_kernel(const float* __restrict__ x) {
    extern __shared__ char dynsm[];
    float* slab   = reinterpret_cast<float*>(dynsm);                 // 8448 B
    uint32_t* stH = reinterpret_cast<uint32_t*>(dynsm + 8448);       // 36992 B
    uint32_t* stL = reinterpret_cast<uint32_t*>(dynsm + 8448 + 36992);

    const int tid = threadIdx.x;
    const int xb  = blockIdx.x * 32;
    const int iy  = blockIdx.y;
    const int b   = blockIdx.z;

    for (int i = tid; i < 64 * 32; i += 256) {
        int c = i >> 5, px = i & 31;
        slab[c * 33 + px] = x[(((b * 64 + c) * 64 + iy) << 6) + xb + px];
    }
    __syncthreads();

    const int px = tid >> 3;
    const int cg = tid & 7;
#pragma unroll
    for (int pair = 0; pair < 4; pair++) {
        int c0 = cg * 8 + pair * 2;
        float f[18];
        feat9(slab[c0 * 33 + px], f);
        feat9(slab[(c0 + 1) * 33 + px], f + 9);
        int wb = px * 289 + cg * 36 + pair * 9;
#pragma unroll
        for (int q = 0; q < 9; q++) {
            __half ah, al, bh, bl;
            split2h(f[2 * q], ah, al);
            split2h(f[2 * q + 1], bh, bl);
            __half2 th = __halves2half2(ah, bh);
            __half2 tl = __halves2half2(al, bl);
            stH[wb + q] = *reinterpret_cast<uint32_t*>(&th);
            stL[wb + q] = *reinterpret_cast<uint32_t*>(&tl);
        }
    }
    __syncthreads();

    const size_t pixbase = ((size_t)((b * PH + iy + 1) * PW + xb + 1)) * CF;
    uint32_t* dH = reinterpret_cast<uint32_t*>(g_Fh + pixbase);
    uint32_t* dL = reinterpret_cast<uint32_t*>(g_Fl + pixbase);
    for (int i = tid; i < 32 * 288; i += 256) {
        int p = i / 288, w = i - p * 288;
        dH[i] = stH[p * 289 + w];
        dL[i] = stL[p * 289 + w];
    }
}

// ---------------------------------------------------------------------------
// border kernel: padded border pixels get features of x = 0
// ---------------------------------------------------------------------------
__global__ __launch_bounds__(256) void border_kernel() {
    int i = blockIdx.x;
    int b = i / 260, r = i - b * 260;
    int py, pxx;
    if (r < 66)        { py = 0;  pxx = r; }
    else if (r < 132)  { py = 65; pxx = r - 66; }
    else { int t = r - 132; py = 1 + (t >> 1); pxx = (t & 1) * 65; }

    float zf[9];
    feat9(0.0f, zf);
    __half zh[9], zl[9];
#pragma unroll
    for (int q = 0; q < 9; q++) split2h(zf[q], zh[q], zl[q]);

    __half* dH = g_Fh + ((size_t)((b * PH + py) * PW + pxx)) * CF;
    __half* dL = g_Fl + ((size_t)((b * PH + py) * PW + pxx)) * CF;
    for (int e = threadIdx.x; e < CF; e += 256) {
        int q = e % 9;
        dH[e] = zh[q];
        dL[e] = zl[q];
    }
}

// ---------------------------------------------------------------------------
// weight fold -> [o][kk], kk = tap*576 + c*9 + ck, source index d = c*9 + tap
// ---------------------------------------------------------------------------
__global__ __launch_bounds__(256) void weight_kernel(
    const float* __restrict__ bw, const float* __restrict__ sw,
    const float* __restrict__ ss) {
    int idx = blockIdx.x * 256 + threadIdx.x;
    if (idx >= OUTC * KTOT) return;
    int o   = idx / KTOT;
    int kk  = idx - o * KTOT;
    int tap = kk / 576;
    int r   = kk - tap * 576;
    int c   = r / 9;
    int ck  = r - c * 9;
    int d   = c * 9 + tap;
    float v = ck ? sw[(o * 576 + d) * 8 + (ck - 1)] * ss[o * 576 + d]
                 : bw[o * 576 + d];
    g_Bf[idx] = __float2half_rn(v);
}

// ---------------------------------------------------------------------------
// GEMM: 128 CTAs, M=128 x N=128 x K=5184, fp16 hi/lo x2 via mma.sync.
// 512 threads (16 warps, 4x4, each m32 x n32). 4-stage cp.async pipeline.
// Per stage (48KB): [Ah 16K][Al 16K][B 16K], rows of 128B, swizzled.
// ---------------------------------------------------------------------------
#define STAGE_BYTES 49152
#define T_AH 0
#define T_AL 16384
#define T_B  32768

__global__ __launch_bounds__(512, 1) void gemm_kernel(float* __restrict__ out) {
    extern __shared__ char dynsm[];
    uint32_t raw  = smem_u32(dynsm);
    uint32_t base = (raw + 1023u) & ~1023u;

    const int tid  = threadIdx.x;
    const int wid  = tid >> 5;
    const int lane = tid & 31;
    const int wm   = wid & 3;
    const int wn   = wid >> 2;
    const int mbase = blockIdx.x * 128;

    // ---- cp.async mapping: row = tid>>2 (0..127), seg = tid&3 (32B quarter)
    const int row = tid >> 2;
    const int seg = tid & 3;
    const int npix = mbase + row;
    const int pb = npix >> 12;
    const int oy = (npix >> 6) & 63;
    const int ox = npix & 63;
    const __half* apH = g_Fh + ((size_t)((pb * PH + oy) * PW + ox)) * CF;
    const __half* apL = g_Fl + ((size_t)((pb * PH + oy) * PW + ox)) * CF;
    const __half* bp  = g_Bf + (size_t)row * KTOT;
    const uint32_t rowterm = (uint32_t)row * 128;
    const uint32_t rowpat  = ((uint32_t)row & 7) << 4;

    auto load_chunk = [&](int kc, int stage) {
        int tap = kc / 9;
        int sub = kc - tap * 9;
        int kh = tap / 3, kw = tap - kh * 3;
        int aoff = (kh * PW + kw) * CF + sub * 64 + seg * 16;  // fp16 elements
        int boff = kc * 64 + seg * 16;
        const char* sAh = (const char*)(apH + aoff);
        const char* sAl = (const char*)(apL + aoff);
        const char* sB  = (const char*)(bp + boff);
        uint32_t sb = base + (uint32_t)stage * STAGE_BYTES + rowterm;
#pragma unroll
        for (int q = 0; q < 2; q++) {
            uint32_t kb = (uint32_t)(seg * 32 + q * 16);
            uint32_t d  = sb + (kb ^ rowpat);
            CP16(d + T_AH, sAh + q * 16);
            CP16(d + T_AL, sAl + q * 16);
            CP16(d + T_B,  sB  + q * 16);
        }
        CP_COMMIT();
    };

    // ---- ldmatrix lane addressing ----
    const int rA  = lane & 15;
    const uint32_t kA = ((uint32_t)(lane >> 4)) * 16;   // bytes
    uint32_t aRow[2], aPat[2];
#pragma unroll
    for (int mt = 0; mt < 2; mt++) {
        int rr = wm * 32 + mt * 16 + rA;
        aRow[mt] = (uint32_t)rr * 128;
        aPat[mt] = ((uint32_t)rr & 7) << 4;
    }
    const int rBl = (lane & 7) + ((lane >> 4) & 1) * 8;
    const uint32_t kB = ((uint32_t)((lane >> 3) & 1)) * 16;
    uint32_t bRow[2], bPat[2];
#pragma unroll
    for (int nt = 0; nt < 2; nt++) {
        int rr = wn * 32 + nt * 16 + rBl;
        bRow[nt] = (uint32_t)rr * 128;
        bPat[nt] = ((uint32_t)rr & 7) << 4;
    }

    float acc[2][4][4];
#pragma unroll
    for (int i = 0; i < 2; i++)
#pragma unroll
        for (int j = 0; j < 4; j++)
#pragma unroll
            for (int q = 0; q < 4; q++) acc[i][j][q] = 0.0f;

    load_chunk(0, 0);
    load_chunk(1, 1);
    load_chunk(2, 2);

    for (int ks = 0; ks < NCHUNK; ks++) {
        CP_WAIT(2);
        __syncthreads();

        if (ks + 3 < NCHUNK) load_chunk(ks + 3, (ks + 3) & 3);
        else CP_COMMIT();   // keep group count consistent for CP_WAIT(2)

        const uint32_t bb = base + (uint32_t)(ks & 3) * STAGE_BYTES;
#pragma unroll
        for (int kk = 0; kk < 4; kk++) {
            uint32_t ah[2][4], al[2][4];
#pragma unroll
            for (int mt = 0; mt < 2; mt++) {
                uint32_t addr = bb + aRow[mt] + (((uint32_t)(kk * 32) + kA) ^ aPat[mt]);
                LDSM4(ah[mt][0], ah[mt][1], ah[mt][2], ah[mt][3], addr + T_AH);
                LDSM4(al[mt][0], al[mt][1], al[mt][2], al[mt][3], addr + T_AL);
            }
#pragma unroll
            for (int nt = 0; nt < 2; nt++) {
                uint32_t addr = bb + bRow[nt] + (((uint32_t)(kk * 32) + kB) ^ bPat[nt]);
                uint32_t bf[4];
                LDSM4(bf[0], bf[1], bf[2], bf[3], addr + T_B);
#pragma unroll
                for (int mt = 0; mt < 2; mt++) {
#pragma unroll
                    for (int sub = 0; sub < 2; sub++) {
                        float* d = acc[mt][nt * 2 + sub];
                        MMA16816(d, ah[mt], bf[sub * 2], bf[sub * 2 + 1]);
                        MMA16816(d, al[mt], bf[sub * 2], bf[sub * 2 + 1]);
                    }
                }
            }
        }
    }
    __syncthreads();

    // ---- epilogue: stage through smem (transpose), coalesced global write --
    float* st = reinterpret_cast<float*>(dynsm + (base - raw));
    const int g  = lane >> 2;
    const int tg = lane & 3;
#pragma unroll
    for (int mt = 0; mt < 2; mt++) {
#pragma unroll
        for (int n8 = 0; n8 < 4; n8++) {
            int m0 = wm * 32 + mt * 16 + g;
            int n0 = wn * 32 + n8 * 8 + tg * 2;
            const float* c = acc[mt][n8];
            st[m0 * 129 + n0]           = c[0];
            st[m0 * 129 + n0 + 1]       = c[1];
            st[(m0 + 8) * 129 + n0]     = c[2];
            st[(m0 + 8) * 129 + n0 + 1] = c[3];
        }
    }
    __syncthreads();

    const int b_ = mbase >> 12;
    const int spb = mbase & 4095;
#pragma unroll
    for (int r = 0; r < 32; r++) {
        int idx = r * 512 + tid;
        int o = idx >> 7;
        int m = idx & 127;
        out[(((size_t)(b_ * OUTC + o)) << 12) + spb + m] = st[m * 129 + o];
    }
}

// ---------------------------------------------------------------------------
extern "C" void kernel_launch(void* const* d_in, const int* in_sizes, int n_in,
                              void* d_out, int out_size) {
    const float* x  = (const float*)d_in[0];
    const float* bw = (const float*)d_in[1];
    const float* sw = (const float*)d_in[2];
    const float* ss = (const float*)d_in[3];
    float* out = (float*)d_out;

    cudaFuncSetAttribute(feat_kernel, cudaFuncAttributeMaxDynamicSharedMemorySize, 90112);
    cudaFuncSetAttribute(gemm_kernel, cudaFuncAttributeMaxDynamicSharedMemorySize, 197632);

    feat_kernel<<<dim3(2, 64, 4), 256, 8448 + 2 * 36992>>>(x);
    border_kernel<<<4 * 260, 256>>>();
    weight_kernel<<<(OUTC * KTOT + 255) / 256, 256>>>(bw, sw, ss);
    gemm_kernel<<<128, 512, 197632>>>(out);
}

// round 5
// speedup vs baseline: 5.8811x; 1.6557x over previous
#include <cuda_runtime.h>
#include <cuda_fp16.h>
#include <cstdint>
#include <math.h>

// ---------------------------------------------------------------------------
// KANConv2d: expanded feature map (silu + 8 uniform cubic B-spline basis
// channels per input channel) -> single 3x3 conv as implicit GEMM (mma.sync).
// Single-pass fp16 (A and B one plane each), fp32 accumulate.
// ---------------------------------------------------------------------------

#define BATCH 4
#define CIN 64
#define OUTC 128
#define PH 66
#define PW 66
#define CF 576          // 64 ch * 9 feats
#define KTOT 5184       // 9 taps * 576
#define NCHUNK 81       // 5184 / 64
#define NSTAGE 6

// device scratch (allocation-free)
__device__ __align__(16) __half g_Ff[BATCH * PH * PW * CF];
__device__ __align__(16) __half g_Bf[OUTC * KTOT];

// ---------------------------------------------------------------------------
__device__ __forceinline__ uint32_t smem_u32(const void* p) {
    uint32_t a;
    asm("{ .reg .u64 t; cvta.to.shared.u64 t, %1; cvt.u32.u64 %0, t; }"
        : "=r"(a) : "l"(p));
    return a;
}

#define CP16(dst, src) \
    asm volatile("cp.async.cg.shared.global [%0], [%1], 16;" \
                 :: "r"(dst), "l"(src) : "memory")
#define CP_COMMIT() asm volatile("cp.async.commit_group;" ::: "memory")
#define CP_WAIT(n)  asm volatile("cp.async.wait_group %0;" :: "n"(n) : "memory")

#define LDSM4(r0, r1, r2, r3, a) \
    asm volatile("ldmatrix.sync.aligned.m8n8.x4.shared.b16 {%0,%1,%2,%3}, [%4];" \
                 : "=r"(r0), "=r"(r1), "=r"(r2), "=r"(r3) : "r"(a))

#define MMA16816(d, a, b0, b1) \
    asm volatile("mma.sync.aligned.m16n8k16.row.col.f32.f16.f16.f32 " \
                 "{%0,%1,%2,%3}, {%4,%5,%6,%7}, {%8,%9}, {%0,%1,%2,%3};" \
                 : "+f"((d)[0]), "+f"((d)[1]), "+f"((d)[2]), "+f"((d)[3]) \
                 : "r"((a)[0]), "r"((a)[1]), "r"((a)[2]), "r"((a)[3]), \
                   "r"(b0), "r"(b1))

// ---------------------------------------------------------------------------
// feature math: silu + 8 uniform cubic B-spline basis values (grid [-2.2,2.2])
// ---------------------------------------------------------------------------
__device__ __forceinline__ void feat9(float v, float* dst) {
    dst[0] = v / (1.0f + __expf(-v));
    float s = (v + 2.2f) * 2.5f;
    int j = (int)floorf(s);
    float B0 = 0.f, B1 = 0.f, B2 = 0.f, B3 = 0.f;
    if (j >= 0 && j <= 10) {
        float u  = (v - (0.4f * (float)j - 2.2f)) * 2.5f;
        float um = 1.0f - u;
        float u2 = u * u, u3 = u2 * u;
        B3 = u3 * (1.0f / 6.0f);
        B2 = (-3.0f * u3 + 3.0f * u2 + 3.0f * u + 1.0f) * (1.0f / 6.0f);
        B1 = (3.0f * u3 - 6.0f * u2 + 4.0f) * (1.0f / 6.0f);
        B0 = um * um * um * (1.0f / 6.0f);
    }
#pragma unroll
    for (int i = 0; i < 8; i++) {
        int rel = j - i;
        dst[1 + i] = (rel == 0) ? B3 : (rel == 1) ? B2 : (rel == 2) ? B1
                   : (rel == 3) ? B0 : 0.0f;
    }
}

// ---------------------------------------------------------------------------
// feat kernel: interior pixels. grid (2, 64, 4) = (x-half, row, batch).
// ---------------------------------------------------------------------------
__global__ __launch_bounds__(256) void feat_kernel(const float* __restrict__ x) {
    extern __shared__ char dynsm[];
    float* slab   = reinterpret_cast<float*>(dynsm);                 // 8448 B
    uint32_t* stH = reinterpret_cast<uint32_t*>(dynsm + 8448);       // 36992 B

    const int tid = threadIdx.x;
    const int xb  = blockIdx.x * 32;
    const int iy  = blockIdx.y;
    const int b   = blockIdx.z;

    for (int i = tid; i < 64 * 32; i += 256) {
        int c = i >> 5, px = i & 31;
        slab[c * 33 + px] = x[(((b * 64 + c) * 64 + iy) << 6) + xb + px];
    }
    __syncthreads();

    const int px = tid >> 3;
    const int cg = tid & 7;
#pragma unroll
    for (int pair = 0; pair < 4; pair++) {
        int c0 = cg * 8 + pair * 2;
        float f[18];
        feat9(slab[c0 * 33 + px], f);
        feat9(slab[(c0 + 1) * 33 + px], f + 9);
        int wb = px * 289 + cg * 36 + pair * 9;
#pragma unroll
        for (int q = 0; q < 9; q++) {
            __half2 th = __halves2half2(__float2half_rn(f[2 * q]),
                                        __float2half_rn(f[2 * q + 1]));
            stH[wb + q] = *reinterpret_cast<uint32_t*>(&th);
        }
    }
    __syncthreads();

    const size_t pixbase = ((size_t)((b * PH + iy + 1) * PW + xb + 1)) * CF;
    uint32_t* dH = reinterpret_cast<uint32_t*>(g_Ff + pixbase);
    for (int i = tid; i < 32 * 288; i += 256) {
        int p = i / 288, w = i - p * 288;
        dH[i] = stH[p * 289 + w];
    }
}

// ---------------------------------------------------------------------------
// border kernel: padded border pixels get features of x = 0
// ---------------------------------------------------------------------------
__global__ __launch_bounds__(256) void border_kernel() {
    int i = blockIdx.x;
    int b = i / 260, r = i - b * 260;
    int py, pxx;
    if (r < 66)        { py = 0;  pxx = r; }
    else if (r < 132)  { py = 65; pxx = r - 66; }
    else { int t = r - 132; py = 1 + (t >> 1); pxx = (t & 1) * 65; }

    float zf[9];
    feat9(0.0f, zf);
    __half zh[9];
#pragma unroll
    for (int q = 0; q < 9; q++) zh[q] = __float2half_rn(zf[q]);

    __half* dH = g_Ff + ((size_t)((b * PH + py) * PW + pxx)) * CF;
    for (int e = threadIdx.x; e < CF; e += 256)
        dH[e] = zh[e % 9];
}

// ---------------------------------------------------------------------------
// weight fold -> [o][kk], kk = tap*576 + c*9 + ck, source index d = c*9 + tap
// ---------------------------------------------------------------------------
__global__ __launch_bounds__(256) void weight_kernel(
    const float* __restrict__ bw, const float* __restrict__ sw,
    const float* __restrict__ ss) {
    int idx = blockIdx.x * 256 + threadIdx.x;
    if (idx >= OUTC * KTOT) return;
    int o   = idx / KTOT;
    int kk  = idx - o * KTOT;
    int tap = kk / 576;
    int r   = kk - tap * 576;
    int c   = r / 9;
    int ck  = r - c * 9;
    int d   = c * 9 + tap;
    float v = ck ? sw[(o * 576 + d) * 8 + (ck - 1)] * ss[o * 576 + d]
                 : bw[o * 576 + d];
    g_Bf[idx] = __float2half_rn(v);
}

// ---------------------------------------------------------------------------
// GEMM: 128 CTAs, M=128 x N=128 x K=5184, fp16 single-pass via mma.sync.
// 512 threads (16 warps, 4x4, each m32 x n32). 6-stage cp.async pipeline.
// Per stage (32KB): [A 16K][B 16K], rows of 128B, swizzled.
// ---------------------------------------------------------------------------
#define STAGE_BYTES 32768
#define T_A 0
#define T_B 16384

__global__ __launch_bounds__(512, 1) void gemm_kernel(float* __restrict__ out) {
    extern __shared__ char dynsm[];
    uint32_t raw  = smem_u32(dynsm);
    uint32_t base = (raw + 1023u) & ~1023u;

    const int tid  = threadIdx.x;
    const int wid  = tid >> 5;
    const int lane = tid & 31;
    const int wm   = wid & 3;
    const int wn   = wid >> 2;
    const int mbase = blockIdx.x * 128;

    // ---- cp.async mapping: row = tid>>2 (0..127), seg = tid&3 (32B quarter)
    const int row = tid >> 2;
    const int seg = tid & 3;
    const int npix = mbase + row;
    const int pb = npix >> 12;
    const int oy = (npix >> 6) & 63;
    const int ox = npix & 63;
    const __half* ap = g_Ff + ((size_t)((pb * PH + oy) * PW + ox)) * CF;
    const __half* bp = g_Bf + (size_t)row * KTOT;
    const uint32_t rowterm = (uint32_t)row * 128;
    const uint32_t rowpat  = ((uint32_t)row & 7) << 4;

    auto load_chunk = [&](int kc, int stage) {
        int tap = kc / 9;
        int sub = kc - tap * 9;
        int kh = tap / 3, kw = tap - kh * 3;
        int aoff = (kh * PW + kw) * CF + sub * 64 + seg * 16;  // fp16 elements
        int boff = kc * 64 + seg * 16;
        const char* sA = (const char*)(ap + aoff);
        const char* sB = (const char*)(bp + boff);
        uint32_t sb = base + (uint32_t)stage * STAGE_BYTES + rowterm;
#pragma unroll
        for (int q = 0; q < 2; q++) {
            uint32_t kb = (uint32_t)(seg * 32 + q * 16);
            uint32_t d  = sb + (kb ^ rowpat);
            CP16(d + T_A, sA + q * 16);
            CP16(d + T_B, sB + q * 16);
        }
        CP_COMMIT();
    };

    // ---- ldmatrix lane addressing ----
    const int rA  = lane & 15;
    const uint32_t kA = ((uint32_t)(lane >> 4)) * 16;   // bytes
    uint32_t aRow[2], aPat[2];
#pragma unroll
    for (int mt = 0; mt < 2; mt++) {
        int rr = wm * 32 + mt * 16 + rA;
        aRow[mt] = (uint32_t)rr * 128;
        aPat[mt] = ((uint32_t)rr & 7) << 4;
    }
    const int rBl = (lane & 7) + ((lane >> 4) & 1) * 8;
    const uint32_t kB = ((uint32_t)((lane >> 3) & 1)) * 16;
    uint32_t bRow[2], bPat[2];
#pragma unroll
    for (int nt = 0; nt < 2; nt++) {
        int rr = wn * 32 + nt * 16 + rBl;
        bRow[nt] = (uint32_t)rr * 128;
        bPat[nt] = ((uint32_t)rr & 7) << 4;
    }

    float acc[2][4][4];
#pragma unroll
    for (int i = 0; i < 2; i++)
#pragma unroll
        for (int j = 0; j < 4; j++)
#pragma unroll
            for (int q = 0; q < 4; q++) acc[i][j][q] = 0.0f;

    // prologue: stages 0..4
#pragma unroll
    for (int s = 0; s < NSTAGE - 1; s++) load_chunk(s, s);

    int stage = 0;
    for (int ks = 0; ks < NCHUNK; ks++) {
        CP_WAIT(4);
        __syncthreads();

        if (ks + NSTAGE - 1 < NCHUNK) {
            int kn = ks + NSTAGE - 1;
            int sn = stage + NSTAGE - 1; if (sn >= NSTAGE) sn -= NSTAGE;
            load_chunk(kn, sn);
        } else {
            CP_COMMIT();   // keep group count consistent for CP_WAIT(4)
        }

        const uint32_t bb = base + (uint32_t)stage * STAGE_BYTES;
#pragma unroll
        for (int kk = 0; kk < 4; kk++) {
            uint32_t af[2][4];
#pragma unroll
            for (int mt = 0; mt < 2; mt++) {
                uint32_t addr = bb + aRow[mt] + (((uint32_t)(kk * 32) + kA) ^ aPat[mt]);
                LDSM4(af[mt][0], af[mt][1], af[mt][2], af[mt][3], addr + T_A);
            }
#pragma unroll
            for (int nt = 0; nt < 2; nt++) {
                uint32_t addr = bb + bRow[nt] + (((uint32_t)(kk * 32) + kB) ^ bPat[nt]);
                uint32_t bf[4];
                LDSM4(bf[0], bf[1], bf[2], bf[3], addr + T_B);
#pragma unroll
                for (int mt = 0; mt < 2; mt++) {
#pragma unroll
                    for (int sub = 0; sub < 2; sub++) {
                        MMA16816(acc[mt][nt * 2 + sub], af[mt],
                                 bf[sub * 2], bf[sub * 2 + 1]);
                    }
                }
            }
        }
        if (++stage == NSTAGE) stage = 0;
    }
    __syncthreads();

    // ---- epilogue: stage through smem (transpose), coalesced global write --
    float* st = reinterpret_cast<float*>(dynsm + (base - raw));
    const int g  = lane >> 2;
    const int tg = lane & 3;
#pragma unroll
    for (int mt = 0; mt < 2; mt++) {
#pragma unroll
        for (int n8 = 0; n8 < 4; n8++) {
            int m0 = wm * 32 + mt * 16 + g;
            int n0 = wn * 32 + n8 * 8 + tg * 2;
            const float* c = acc[mt][n8];
            st[m0 * 129 + n0]           = c[0];
            st[m0 * 129 + n0 + 1]       = c[1];
            st[(m0 + 8) * 129 + n0]     = c[2];
            st[(m0 + 8) * 129 + n0 + 1] = c[3];
        }
    }
    __syncthreads();

    const int b_ = mbase >> 12;
    const int spb = mbase & 4095;
#pragma unroll
    for (int r = 0; r < 32; r++) {
        int idx = r * 512 + tid;
        int o = idx >> 7;
        int m = idx & 127;
        out[(((size_t)(b_ * OUTC + o)) << 12) + spb + m] = st[m * 129 + o];
    }
}

// ---------------------------------------------------------------------------
extern "C" void kernel_launch(void* const* d_in, const int* in_sizes, int n_in,
                              void* d_out, int out_size) {
    const float* x  = (const float*)d_in[0];
    const float* bw = (const float*)d_in[1];
    const float* sw = (const float*)d_in[2];
    const float* ss = (const float*)d_in[3];
    float* out = (float*)d_out;

    cudaFuncSetAttribute(feat_kernel, cudaFuncAttributeMaxDynamicSharedMemorySize, 50176);
    cudaFuncSetAttribute(gemm_kernel, cudaFuncAttributeMaxDynamicSharedMemorySize, 197632);

    feat_kernel<<<dim3(2, 64, 4), 256, 8448 + 36992>>>(x);
    border_kernel<<<4 * 260, 256>>>();
    weight_kernel<<<(OUTC * KTOT + 255) / 256, 256>>>(bw, sw, ss);
    gemm_kernel<<<128, 512, 197632>>>(out);
}